// round 15
// baseline (speedup 1.0000x reference)
#include <cuda_runtime.h>

#define EPS 0.1f
#define BB 64
#define II 1024
#define HH 4096
#define OO 256

__device__ float g_w1norm[HH];

// ---------------------------------------------------------------------------
// K1: W1_norm[j] = sum_i |W1[j,i]|
//   512 blocks x 256 threads; one warp per W1 row; 8 outstanding LDG.128/thread
// ---------------------------------------------------------------------------
__global__ void k_w1norm(const float* __restrict__ W1) {
    const int lid = threadIdx.x & 31;
    const int row = blockIdx.x * 8 + (threadIdx.x >> 5);
    const float4* r = reinterpret_cast<const float4*>(W1 + (size_t)row * II);
    float4 v[8];
    #pragma unroll
    for (int k = 0; k < 8; k++) v[k] = r[lid + k * 32];
    float s = 0.f;
    #pragma unroll
    for (int k = 0; k < 8; k++)
        s += fabsf(v[k].x) + fabsf(v[k].y) + fabsf(v[k].z) + fabsf(v[k].w);
    #pragma unroll
    for (int o = 16; o; o >>= 1) s += __shfl_down_sync(0xffffffffu, s, o);
    if (lid == 0) g_w1norm[row] = s;
}

// ---------------------------------------------------------------------------
// K2: fused nn_output + pert, 1D grid of 256 + 1024 blocks, 256 threads
//   bid <  256 : nn_output[b,i] = 4096*sum_j W2[i,j] + bias2[i]  (i = bid)
//                (4 MB read hides under the pert store stream)
//   bid >= 256 : pert[b,i,j] = -EPS*yf[b,i]*sign(W2[i,j])*W1_norm[j]
//                p = bid-256, i = p>>2, chunk = p&3; each thread owns one
//                float4 of s; streams 64 coalesced STG.128 (.cs)
// ---------------------------------------------------------------------------
__global__ void k_main(const int* __restrict__ y,
                       const float* __restrict__ W2,
                       const float* __restrict__ bias2,
                       float* __restrict__ out_nn,
                       float* __restrict__ pert) {
    const int bid = blockIdx.x;
    const int lid = threadIdx.x & 31;
    const int wid = threadIdx.x >> 5;

    if (bid < 256) {
        // ---- nn_output row i ----
        const int i = bid;
        const float4* r = reinterpret_cast<const float4*>(W2 + (size_t)i * HH);
        float4 v[4];
        #pragma unroll
        for (int k = 0; k < 4; k++) v[k] = r[threadIdx.x + k * 256];
        float s = 0.f;
        #pragma unroll
        for (int k = 0; k < 4; k++) s += v[k].x + v[k].y + v[k].z + v[k].w;

        __shared__ float sm[8];
        #pragma unroll
        for (int o = 16; o; o >>= 1) s += __shfl_down_sync(0xffffffffu, s, o);
        if (lid == 0) sm[wid] = s;
        __syncthreads();
        __shared__ float total;
        if (threadIdx.x < 8) {
            float t = sm[threadIdx.x];
            #pragma unroll
            for (int o = 4; o; o >>= 1) t += __shfl_down_sync(0xffu, t, o);
            if (threadIdx.x == 0) total = t * (float)HH + bias2[i];
        }
        __syncthreads();
        if (threadIdx.x < BB)
            out_nn[(size_t)threadIdx.x * OO + i] = total;
        return;
    }

    // ---- pert ----
    const int p  = bid - 256;
    const int i  = p >> 2;
    const int j4 = (p & 3) * 256 + threadIdx.x;

    __shared__ float yf[BB];
    if (threadIdx.x < BB) yf[threadIdx.x] = (float)y[(size_t)threadIdx.x * OO + i];
    __syncthreads();

    float4 w = reinterpret_cast<const float4*>(W2 + (size_t)i * HH)[j4];
    float4 n = reinterpret_cast<const float4*>(g_w1norm)[j4];
    float4 s;
    s.x = -EPS * ((w.x > 0.f) ? 1.f : (w.x < 0.f) ? -1.f : 0.f) * n.x;
    s.y = -EPS * ((w.y > 0.f) ? 1.f : (w.y < 0.f) ? -1.f : 0.f) * n.y;
    s.z = -EPS * ((w.z > 0.f) ? 1.f : (w.z < 0.f) ? -1.f : 0.f) * n.z;
    s.w = -EPS * ((w.w > 0.f) ? 1.f : (w.w < 0.f) ? -1.f : 0.f) * n.w;

    float* base = pert + (size_t)i * HH + (size_t)j4 * 4;
    #pragma unroll 8
    for (int b = 0; b < BB; b++) {
        float yb = yf[b];
        float4 o;
        o.x = yb * s.x; o.y = yb * s.y; o.z = yb * s.z; o.w = yb * s.w;
        __stcs(reinterpret_cast<float4*>(base + (size_t)b * OO * HH), o);
    }
}

// ---------------------------------------------------------------------------
// launch
// inputs: x[0] (unused), y[1], W1[2], W2[3], bias1[4] (unused), bias2[5]
// out layout: nn_output [B*O] then pert [B*O*H]
// ---------------------------------------------------------------------------
extern "C" void kernel_launch(void* const* d_in, const int* in_sizes, int n_in,
                              void* d_out, int out_size) {
    const int*   y     = (const int*)d_in[1];
    const float* W1    = (const float*)d_in[2];
    const float* W2    = (const float*)d_in[3];
    const float* bias2 = (const float*)d_in[5];

    float* out_nn = (float*)d_out;
    float* pert   = out_nn + (size_t)BB * OO;

    k_w1norm<<<512, 256>>>(W1);
    k_main<<<256 + 1024, 256>>>(y, W2, bias2, out_nn, pert);
}

// round 16
// speedup vs baseline: 1.0329x; 1.0329x over previous
#include <cuda_runtime.h>

#define EPS 0.1f
#define BB 64
#define II 1024
#define HH 4096
#define OO 256

__device__ float g_w1norm[HH];

// ---------------------------------------------------------------------------
// K1: W1_norm[j] = sum_i |W1[j,i]|
//   2048 blocks x 64 threads (2 warps); one warp per row; 8 LDG.128/thread
//   in flight. Fine-grained blocks minimize wave imbalance. Fires the PDL
//   trigger at entry so k_main's blocks launch (and load W2/y) while this
//   kernel streams W1.
// ---------------------------------------------------------------------------
__global__ void k_w1norm(const float* __restrict__ W1) {
#if __CUDA_ARCH__ >= 900
    cudaTriggerProgrammaticLaunchCompletion();
#endif
    const int lid = threadIdx.x & 31;
    const int row = blockIdx.x * 2 + (threadIdx.x >> 5);
    const float4* r = reinterpret_cast<const float4*>(W1 + (size_t)row * II);
    float4 v[8];
    #pragma unroll
    for (int k = 0; k < 8; k++) v[k] = r[lid + k * 32];
    float s = 0.f;
    #pragma unroll
    for (int k = 0; k < 8; k++)
        s += fabsf(v[k].x) + fabsf(v[k].y) + fabsf(v[k].z) + fabsf(v[k].w);
    #pragma unroll
    for (int o = 16; o; o >>= 1) s += __shfl_down_sync(0xffffffffu, s, o);
    if (lid == 0) g_w1norm[row] = s;
}

// ---------------------------------------------------------------------------
// K2: fused nn_output + pert — best-measured structure (45.568us, twice).
//   grid = 256 + 1024 blocks, 256 threads.
//   bid <  256 : nn_output row i = bid (independent of w1norm -> no grid sync)
//   bid >= 256 : pert unit p = bid-256 (i = p>>2, chunk = p&3):
//                load W2/y first (independent), THEN gridDependencySync,
//                THEN read g_w1norm; stream 64 coalesced STG.128 (.cs).
// ---------------------------------------------------------------------------
__global__ void k_main(const int* __restrict__ y,
                       const float* __restrict__ W2,
                       const float* __restrict__ bias2,
                       float* __restrict__ out_nn,
                       float* __restrict__ pert) {
    const int bid = blockIdx.x;
    const int lid = threadIdx.x & 31;
    const int wid = threadIdx.x >> 5;

    if (bid < 256) {
        // ---- nn_output row i (no w1norm dependency, runs fully overlapped) ----
        const int i = bid;
        const float4* r = reinterpret_cast<const float4*>(W2 + (size_t)i * HH);
        float4 v[4];
        #pragma unroll
        for (int k = 0; k < 4; k++) v[k] = r[threadIdx.x + k * 256];
        float s = 0.f;
        #pragma unroll
        for (int k = 0; k < 4; k++) s += v[k].x + v[k].y + v[k].z + v[k].w;

        __shared__ float sm[8];
        #pragma unroll
        for (int o = 16; o; o >>= 1) s += __shfl_down_sync(0xffffffffu, s, o);
        if (lid == 0) sm[wid] = s;
        __syncthreads();
        __shared__ float total;
        if (threadIdx.x < 8) {
            float t = sm[threadIdx.x];
            #pragma unroll
            for (int o = 4; o; o >>= 1) t += __shfl_down_sync(0xffu, t, o);
            if (threadIdx.x == 0) total = t * (float)HH + bias2[i];
        }
        __syncthreads();
        if (threadIdx.x < BB)
            out_nn[(size_t)threadIdx.x * OO + i] = total;
        return;
    }

    // ---- pert ----
    const int p  = bid - 256;
    const int i  = p >> 2;
    const int j4 = (p & 3) * 256 + threadIdx.x;

    __shared__ float yf[BB];
    if (threadIdx.x < BB) yf[threadIdx.x] = (float)y[(size_t)threadIdx.x * OO + i];

    // independent load first (overlaps with w1norm's tail under PDL)
    float4 w = reinterpret_cast<const float4*>(W2 + (size_t)i * HH)[j4];

#if __CUDA_ARCH__ >= 900
    cudaGridDependencySynchronize();   // wait for k_w1norm completion+visibility
#endif
    __syncthreads();                    // covers yf

    float4 n = reinterpret_cast<const float4*>(g_w1norm)[j4];
    float4 s;
    s.x = -EPS * ((w.x > 0.f) ? 1.f : (w.x < 0.f) ? -1.f : 0.f) * n.x;
    s.y = -EPS * ((w.y > 0.f) ? 1.f : (w.y < 0.f) ? -1.f : 0.f) * n.y;
    s.z = -EPS * ((w.z > 0.f) ? 1.f : (w.z < 0.f) ? -1.f : 0.f) * n.z;
    s.w = -EPS * ((w.w > 0.f) ? 1.f : (w.w < 0.f) ? -1.f : 0.f) * n.w;

    float* base = pert + (size_t)i * HH + (size_t)j4 * 4;
    #pragma unroll 8
    for (int b = 0; b < BB; b++) {
        float yb = yf[b];
        float4 o;
        o.x = yb * s.x; o.y = yb * s.y; o.z = yb * s.z; o.w = yb * s.w;
        __stcs(reinterpret_cast<float4*>(base + (size_t)b * OO * HH), o);
    }
}

// ---------------------------------------------------------------------------
// launch — w1norm, then k_main as a programmatic dependent launch
// inputs: x[0] (unused), y[1], W1[2], W2[3], bias1[4] (unused), bias2[5]
// out layout: nn_output [B*O] then pert [B*O*H]
// ---------------------------------------------------------------------------
extern "C" void kernel_launch(void* const* d_in, const int* in_sizes, int n_in,
                              void* d_out, int out_size) {
    const int*   y     = (const int*)d_in[1];
    const float* W1    = (const float*)d_in[2];
    const float* W2    = (const float*)d_in[3];
    const float* bias2 = (const float*)d_in[5];

    float* out_nn = (float*)d_out;
    float* pert   = out_nn + (size_t)BB * OO;

    k_w1norm<<<2048, 64>>>(W1);

    cudaLaunchAttribute attrs[1];
    attrs[0].id = cudaLaunchAttributeProgrammaticStreamSerialization;
    attrs[0].val.programmaticStreamSerializationAllowed = 1;

    cudaLaunchConfig_t cfg = {};
    cfg.gridDim  = dim3(256 + 1024);
    cfg.blockDim = dim3(256);
    cfg.dynamicSmemBytes = 0;
    cfg.stream   = 0;
    cfg.attrs    = attrs;
    cfg.numAttrs = 1;
    cudaLaunchKernelEx(&cfg, k_main, y, W2, bias2, out_nn, pert);
}